// round 16
// baseline (speedup 1.0000x reference)
#include <cuda_runtime.h>
#include <cuda_bf16.h>
#include <cuda_fp16.h>
#include <cstdint>
#include <math.h>

#define N_HEADS 16
#define HIDDEN  1024
#define HS      64
#define BATCH   2
#define SEQ     2048
#define M_ROWS  (BATCH * SEQ)      // 4096
#define N_COLS  (3 * HIDDEN)       // 3072

// fp16 copies of the GEMM inputs (prepass output)
__device__ __half g_xh[(size_t)M_ROWS * HIDDEN];
__device__ __half g_wh[(size_t)HIDDEN * N_COLS];
// Attention operands written by the GEMM epilogue (per (b*16+h) head):
//   Q: pre-scaled x0.125, single fp16, [t][d]
//   K: single fp16, [t][d]
//   V: single fp16, [d][t]
#define HEADELEMS ((size_t)SEQ * HS)
__device__ __half g_qh[(size_t)BATCH * N_HEADS * HEADELEMS];
__device__ __half g_kh[(size_t)BATCH * N_HEADS * HEADELEMS];
__device__ __half g_vh[(size_t)BATCH * N_HEADS * HEADELEMS];

// ---------------------------------------------------------------------------
// Helpers
// ---------------------------------------------------------------------------
__device__ __forceinline__ uint32_t smem_u32(const void* p) {
    uint32_t a;
    asm("{ .reg .u64 t; cvta.to.shared.u64 t, %1; cvt.u32.u64 %0, t; }"
        : "=r"(a) : "l"(p));
    return a;
}
__device__ __forceinline__ void mma_fp16(float* d, const uint32_t* a,
                                         const uint32_t* b) {
    asm volatile(
        "mma.sync.aligned.m16n8k16.row.col.f32.f16.f16.f32 "
        "{%0,%1,%2,%3}, {%4,%5,%6,%7}, {%8,%9}, {%0,%1,%2,%3};"
        : "+f"(d[0]), "+f"(d[1]), "+f"(d[2]), "+f"(d[3])
        : "r"(a[0]), "r"(a[1]), "r"(a[2]), "r"(a[3]),
          "r"(b[0]), "r"(b[1]));
}
__device__ __forceinline__ void ldsm_x4(uint32_t& r0, uint32_t& r1,
                                        uint32_t& r2, uint32_t& r3,
                                        uint32_t addr) {
    asm volatile("ldmatrix.sync.aligned.m8n8.x4.shared.b16 {%0,%1,%2,%3}, [%4];"
                 : "=r"(r0), "=r"(r1), "=r"(r2), "=r"(r3) : "r"(addr));
}
__device__ __forceinline__ void ldsm_x4_t(uint32_t& r0, uint32_t& r1,
                                          uint32_t& r2, uint32_t& r3,
                                          uint32_t addr) {
    asm volatile("ldmatrix.sync.aligned.m8n8.x4.trans.shared.b16 {%0,%1,%2,%3}, [%4];"
                 : "=r"(r0), "=r"(r1), "=r"(r2), "=r"(r3) : "r"(addr));
}
__device__ __forceinline__ uint32_t pack_h2(float x, float y) {
    __half2 h = __floats2half2_rn(x, y);
    return *reinterpret_cast<uint32_t*>(&h);
}
__device__ __forceinline__ void cp16(uint32_t dst, const void* src) {
    asm volatile("cp.async.cg.shared.global [%0], [%1], 16;"
                 :: "r"(dst), "l"(src) : "memory");
}
#define CP_COMMIT() asm volatile("cp.async.commit_group;" ::: "memory")
#define CP_WAIT1()  asm volatile("cp.async.wait_group 1;" ::: "memory")
#define CP_WAIT0()  asm volatile("cp.async.wait_group 0;" ::: "memory")

// ---------------------------------------------------------------------------
// Kernel 0: fp32 -> fp16 prepass for x and W.
// ---------------------------------------------------------------------------
#define NX4 ((size_t)M_ROWS * HIDDEN / 4)   // 1048576
#define NW4 ((size_t)HIDDEN * N_COLS / 4)   // 786432

__global__ void __launch_bounds__(256) cvt_half(const float* __restrict__ x,
                                                const float* __restrict__ W) {
    size_t i = (size_t)blockIdx.x * 256 + threadIdx.x;
    if (i < NX4) {
        float4 v = ((const float4*)x)[i];
        __half2* dst = (__half2*)(g_xh + i * 4);
        dst[0] = __floats2half2_rn(v.x, v.y);
        dst[1] = __floats2half2_rn(v.z, v.w);
    } else if (i < NX4 + NW4) {
        size_t j = i - NX4;
        float4 v = ((const float4*)W)[j];
        __half2* dst = (__half2*)(g_wh + j * 4);
        dst[0] = __floats2half2_rn(v.x, v.y);
        dst[1] = __floats2half2_rn(v.z, v.w);
    }
}

// ---------------------------------------------------------------------------
// Kernel 1: QKV GEMM via mma.sync fp16 m16n8k16 with ldmatrix fragments.
// RETILED: 64x128 CTA tile, 8 warps (2M x 4N -> warp tile 32x32),
// 3 CTAs/SM (was 128x128 @ 2) to cut wave quantization (1536 CTAs / 444
// slots = 3.46 waves of ~27us vs 2.59 waves of ~36us).
// A tile: [64 m][32 k] halfs, row stride 80B (conflict-free ldmatrix.x4).
// B tile: [32 k][128 n] halfs, 256B rows, swizzle col^((k&7)<<4).
// Epilogue: bias + reshape scatter:
//   Q third: scaled x0.125, single fp16 -> g_qh [t][d]
//   K third: single fp16 -> g_kh [t][d]
//   V third: single fp16 -> g_vh [d][t]
// Reshape algebra: g = 3r + c/1024; e = c%1024; u=g>>11; t=g&2047;
// h=e&15; d=e>>4.
// ---------------------------------------------------------------------------
#define GBK   32
#define GNIT  (HIDDEN / GBK)          // 32
#define CSTR  132
#define AST_B 5120                    // A stage bytes (64 * 80)
#define STG_B 13312                   // A (5120) + B (8192), 128B aligned
#define GEMM_SMEM_BYTES (CSTR * 64 * 4)    // 33792 >= 2*13312 = 26624

__global__ void __launch_bounds__(256, 3) qkv_gemm_tc(const float* __restrict__ bias)
{
    extern __shared__ char smc[];
    const uint32_t sbase = smem_u32(smc);
    const int tid  = threadIdx.x;
    const int lane = tid & 31;
    const int wid  = tid >> 5;
    const int wm   = wid & 1;          // 2 warps along M (32 rows each)
    const int wn   = wid >> 1;         // 4 warps along N (32 cols each)
    const int m0 = blockIdx.y * 64, n0 = blockIdx.x * 128;
    const int lr = lane >> 2, lc = lane & 3;

    // cp.async mapping: 1 A-chunk + 2 B-chunks (16B each) per thread
    const int am = tid >> 2, ac = tid & 3;         // A: 64 rows x 4 chunks
    const uint32_t a_dst = (uint32_t)(am * 80 + ac * 16);
    const __half* a_src = g_xh + (size_t)(m0 + am) * HIDDEN + ac * 8;
    uint32_t b_dst[2];
    const __half* b_src[2];
    #pragma unroll
    for (int i = 0; i < 2; i++) {
        int id = tid + i * 256;
        int bk = id >> 4, bc = id & 15;            // B: 32 rows x 16 chunks
        b_dst[i] = (uint32_t)(AST_B + bk * 256 + ((bc * 16) ^ ((bk & 7) << 4)));
        b_src[i] = g_wh + (size_t)bk * N_COLS + n0 + bc * 8;
    }

    // ldmatrix lane decomposition (g = matrix index, r = row within matrix)
    const int g = lane >> 3, r = lane & 7;
    const uint32_t a_lane = (uint32_t)((wm * 32 + ((g & 1) << 3) + r) * 80
                                       + (((g >> 1) << 3) << 1));
    const uint32_t b_rowb  = (uint32_t)((((g & 1) << 3) + r) * 256);
    const uint32_t b_colh0 = (uint32_t)(wn * 32 + ((g >> 1) << 3));
    const uint32_t b_xor   = (uint32_t)(r << 4);

    float acc[2][4][4] = {};

    // Prologue: stage 0
    cp16(sbase + a_dst, a_src);
    #pragma unroll
    for (int i = 0; i < 2; i++) cp16(sbase + b_dst[i], b_src[i]);
    CP_COMMIT();

    for (int it = 0; it < GNIT; ++it) {
        const uint32_t buf = (uint32_t)(it & 1) * STG_B;
        if (it + 1 < GNIT) {
            const uint32_t nb = (uint32_t)((it + 1) & 1) * STG_B;
            cp16(sbase + nb + a_dst, a_src + (it + 1) * GBK);
            #pragma unroll
            for (int i = 0; i < 2; i++)
                cp16(sbase + nb + b_dst[i], b_src[i] + (size_t)(it + 1) * GBK * N_COLS);
            CP_COMMIT();
            CP_WAIT1();
        } else {
            CP_WAIT0();
        }
        __syncthreads();

        #pragma unroll
        for (int ks = 0; ks < 2; ks++) {
            uint32_t bf[4][2];
            #pragma unroll
            for (int nblk = 0; nblk < 2; nblk++) {
                uint32_t baddr = sbase + buf + AST_B + b_rowb + (uint32_t)(ks * 4096)
                               + ((((b_colh0 + nblk * 16) << 1)) ^ b_xor);
                uint32_t r0, r1, r2, r3;
                ldsm_x4_t(r0, r1, r2, r3, baddr);
                bf[nblk * 2 + 0][0] = r0; bf[nblk * 2 + 0][1] = r1;
                bf[nblk * 2 + 1][0] = r2; bf[nblk * 2 + 1][1] = r3;
            }
            #pragma unroll
            for (int mf = 0; mf < 2; mf++) {
                uint32_t af[4];
                ldsm_x4(af[0], af[1], af[2], af[3],
                        sbase + buf + a_lane + mf * 1280 + ks * 32);
                #pragma unroll
                for (int nf = 0; nf < 4; nf++)
                    mma_fp16(acc[mf][nf], af, bf[nf]);
            }
        }
        __syncthreads();
    }

    // ---- Epilogue via smem (64 rows x 128 cols) ----
    float* Cs = (float*)smc;
    #pragma unroll
    for (int mf = 0; mf < 2; mf++) {
        const int rr = wm * 32 + mf * 16 + lr;
        #pragma unroll
        for (int nf = 0; nf < 4; nf++) {
            const int c = wn * 32 + nf * 8 + 2 * lc;
            *(float2*)&Cs[rr * CSTR + c]       = make_float2(acc[mf][nf][0], acc[mf][nf][1]);
            *(float2*)&Cs[(rr + 8) * CSTR + c] = make_float2(acc[mf][nf][2], acc[mf][nf][3]);
        }
    }
    __syncthreads();

    {
        const int rr = tid >> 2;            // 0..63 local row
        const int quarter = tid & 3;        // 4 heads per thread
        const int rglob = m0 + rr;
        const int gg = 3 * rglob + (n0 >> 10);
        const int u = gg >> 11, t = gg & 2047;
        const int d0 = (n0 & 1023) >> 4;
        const int kind = u >> 1;            // 0=Q, 1=K, 2=V
        const int bb = u & 1;               // batch
        #pragma unroll
        for (int j = 0; j < 4; j++) {
            const int hh = quarter * 4 + j;
            float o[8];
            #pragma unroll
            for (int e = 0; e < 8; e++)
                o[e] = Cs[rr * CSTR + hh + 16 * e] + __ldg(&bias[n0 + hh + 16 * e]);
            const size_t head = (size_t)(bb * 16 + hh) * HEADELEMS;
            if (kind == 2) {
                // V: single fp16, [d][t]
                #pragma unroll
                for (int e = 0; e < 8; e++)
                    g_vh[head + (size_t)(d0 + e) * SEQ + t] = __float2half_rn(o[e]);
            } else {
                // Q (scaled) or K: single fp16, [t][d]
                const float sc = (kind == 0) ? 0.125f : 1.0f;
                uint32_t kk[4];
                #pragma unroll
                for (int p = 0; p < 4; p++)
                    kk[p] = pack_h2(o[2 * p] * sc, o[2 * p + 1] * sc);
                __half* dst = (kind == 0) ? g_qh : g_kh;
                *(uint4*)(dst + head + (size_t)t * HS + d0) =
                    make_uint4(kk[0], kk[1], kk[2], kk[3]);
            }
        }
    }
}

// ---------------------------------------------------------------------------
// Kernel 2: flash attention via mma.sync fp16 m16n8k16 (unchanged from R15).
// Q, K, V, P all single fp16: QK = 1 mma, PV = 1 mma -> 64 mma/warp-tile.
// SMEM (u32): Q 0..4095; KV double buffers at 4096 + buf*4096:
//   K +0 (2048), V +2048 (2048). Total 12288 u32 = 48KB.
// ---------------------------------------------------------------------------
#define ATT_SMEM_BYTES (12288 * 4)

__global__ void __launch_bounds__(256, 2) attn_mma(float* __restrict__ out) {
    extern __shared__ uint32_t sm[];
    const uint32_t sb = smem_u32(sm);
    uint32_t* Qs = sm;

    const int tid  = threadIdx.x;
    const int lane = tid & 31;
    const int w    = tid >> 5;          // warp 0..7, rows [16w,16w+16)
    const int lr   = lane >> 2, lc = lane & 3;
    const int qtile = (int)(gridDim.x - 1) - (int)blockIdx.x;  // long CTAs first
    const int h = blockIdx.y, b = blockIdx.z;
    const int q0 = qtile * 128;

    const size_t head = (size_t)(b * 16 + h) * HEADELEMS;
    const __half* qhg = g_qh + head;
    const __half* khg = g_kh + head;
    const __half* vhg = g_vh + head;

    uint32_t kv_dst[2];
    int      kv_row[2], kv_c[2];
    #pragma unroll
    for (int i = 0; i < 2; i++) {
        int id = tid + i * 256;
        kv_row[i] = id >> 3;
        kv_c[i]   = id & 7;
        kv_dst[i] = (uint32_t)((kv_row[i] * 32 + ((kv_c[i] ^ (kv_row[i] & 7)) << 2)) * 4);
    }

    // ---- Prologue: Q + KV tile 0 (one group) ----
    #pragma unroll
    for (int i = 0; i < 4; i++) {
        int id = tid + i * 256;
        int rq = id >> 3, cq = id & 7;
        uint32_t d = (uint32_t)((rq * 32 + ((cq ^ (rq & 7)) << 2)) * 4);
        cp16(sb + d, qhg + (size_t)(q0 + rq) * HS + cq * 8);
    }
    #pragma unroll
    for (int i = 0; i < 2; i++) {
        uint32_t base = sb + 4096 * 4;
        cp16(base + kv_dst[i],        khg + (size_t)kv_row[i] * HS + kv_c[i] * 8);
        cp16(base + 8192 + kv_dst[i], vhg + (size_t)kv_row[i] * SEQ + kv_c[i] * 8);
    }
    CP_COMMIT();

    float oacc[8][4];
    #pragma unroll
    for (int j = 0; j < 8; j++)
        #pragma unroll
        for (int k = 0; k < 4; k++) oacc[j][k] = 0.0f;
    float m0 = -1e30f, m1 = -1e30f, l0 = 0.0f, l1 = 0.0f;

    const uint32_t xmask = (uint32_t)lr << 2;

    const int nkt = 2 * qtile + 2;
    for (int kt = 0; kt < nkt; kt++) {
        const int k0g = kt * 64;
        if (kt + 1 < nkt) {
            const int k0n = (kt + 1) * 64;
            const uint32_t base = sb + (4096 + ((kt + 1) & 1) * 4096) * 4;
            #pragma unroll
            for (int i = 0; i < 2; i++) {
                cp16(base + kv_dst[i],        khg + (size_t)(k0n + kv_row[i]) * HS + kv_c[i] * 8);
                cp16(base + 8192 + kv_dst[i], vhg + (size_t)kv_row[i] * SEQ + k0n + kv_c[i] * 8);
            }
            CP_COMMIT();
            CP_WAIT1();
        } else {
            CP_WAIT0();
        }
        __syncthreads();

        if (k0g <= q0 + 16 * w + 15) {
            const uint32_t* Kb = sm + 4096 + (kt & 1) * 4096;
            const uint32_t* Vb = Kb + 2048;

            float sacc[8][4];
            #pragma unroll
            for (int j = 0; j < 8; j++)
                #pragma unroll
                for (int k = 0; k < 4; k++) sacc[j][k] = 0.0f;

            const int r = 16 * w + lr;
            const uint32_t qbase = r * 32;
            #pragma unroll
            for (int ks = 0; ks < 4; ks++) {
                const uint32_t c1x = ((uint32_t)(8 * ks + lc)) ^ xmask;
                const uint32_t c2x = ((uint32_t)(8 * ks + lc + 4)) ^ xmask;
                uint32_t aq[4];
                aq[0] = Qs[qbase + c1x];
                aq[1] = Qs[qbase + 256 + c1x];
                aq[2] = Qs[qbase + c2x];
                aq[3] = Qs[qbase + 256 + c2x];
                #pragma unroll
                for (int j = 0; j < 8; j++) {
                    const uint32_t nb = (uint32_t)(8 * j + lr) * 32;
                    uint32_t bh[2] = { Kb[nb + c1x], Kb[nb + c2x] };
                    mma_fp16(sacc[j], aq, bh);
                }
            }

            const int row0 = q0 + 16 * w + lr;
            if (k0g + 63 > q0 + 16 * w) {
                #pragma unroll
                for (int j = 0; j < 8; j++) {
                    const int c0 = k0g + 8 * j + 2 * lc;
                    if (c0 > row0)         sacc[j][0] = -1e30f;
                    if (c0 + 1 > row0)     sacc[j][1] = -1e30f;
                    if (c0 > row0 + 8)     sacc[j][2] = -1e30f;
                    if (c0 + 1 > row0 + 8) sacc[j][3] = -1e30f;
                }
            }

            float ml0 = -1e30f, ml1 = -1e30f;
            #pragma unroll
            for (int j = 0; j < 8; j++) {
                ml0 = fmaxf(ml0, fmaxf(sacc[j][0], sacc[j][1]));
                ml1 = fmaxf(ml1, fmaxf(sacc[j][2], sacc[j][3]));
            }
            ml0 = fmaxf(ml0, __shfl_xor_sync(0xffffffffu, ml0, 1));
            ml0 = fmaxf(ml0, __shfl_xor_sync(0xffffffffu, ml0, 2));
            ml1 = fmaxf(ml1, __shfl_xor_sync(0xffffffffu, ml1, 1));
            ml1 = fmaxf(ml1, __shfl_xor_sync(0xffffffffu, ml1, 2));

            const float mn0 = fmaxf(m0, ml0), mn1 = fmaxf(m1, ml1);
            const float fac0 = __expf(m0 - mn0), fac1 = __expf(m1 - mn1);
            float ls0 = 0.0f, ls1 = 0.0f;
            #pragma unroll
            for (int j = 0; j < 8; j++) {
                float p0 = __expf(sacc[j][0] - mn0);
                float p1 = __expf(sacc[j][1] - mn0);
                float p2 = __expf(sacc[j][2] - mn1);
                float p3 = __expf(sacc[j][3] - mn1);
                sacc[j][0] = p0; sacc[j][1] = p1; sacc[j][2] = p2; sacc[j][3] = p3;
                ls0 += p0 + p1; ls1 += p2 + p3;
            }
            ls0 += __shfl_xor_sync(0xffffffffu, ls0, 1);
            ls0 += __shfl_xor_sync(0xffffffffu, ls0, 2);
            ls1 += __shfl_xor_sync(0xffffffffu, ls1, 1);
            ls1 += __shfl_xor_sync(0xffffffffu, ls1, 2);
            l0 = l0 * fac0 + ls0;
            l1 = l1 * fac1 + ls1;
            m0 = mn0; m1 = mn1;

            #pragma unroll
            for (int j = 0; j < 8; j++) {
                oacc[j][0] *= fac0; oacc[j][1] *= fac0;
                oacc[j][2] *= fac1; oacc[j][3] *= fac1;
            }

            #pragma unroll
            for (int ks = 0; ks < 4; ks++) {
                uint32_t pf[4];
                pf[0] = pack_h2(sacc[2 * ks][0],     sacc[2 * ks][1]);
                pf[1] = pack_h2(sacc[2 * ks][2],     sacc[2 * ks][3]);
                pf[2] = pack_h2(sacc[2 * ks + 1][0], sacc[2 * ks + 1][1]);
                pf[3] = pack_h2(sacc[2 * ks + 1][2], sacc[2 * ks + 1][3]);
                const uint32_t c1x = ((uint32_t)(8 * ks + lc)) ^ xmask;
                const uint32_t c2x = ((uint32_t)(8 * ks + lc + 4)) ^ xmask;
                #pragma unroll
                for (int j = 0; j < 8; j++) {
                    const uint32_t nb = (uint32_t)(8 * j + lr) * 32;
                    uint32_t bv[2] = { Vb[nb + c1x], Vb[nb + c2x] };
                    mma_fp16(oacc[j], pf, bv);
                }
            }
        }
        __syncthreads();
    }

    // ---- Write O, normalized ----
    const float inv0 = 1.0f / l0, inv1 = 1.0f / l1;
    const int row = q0 + 16 * w + lr;
    float* ob0 = out + ((size_t)(b * SEQ + row)) * HIDDEN + h * HS;
    float* ob1 = out + ((size_t)(b * SEQ + row + 8)) * HIDDEN + h * HS;
    #pragma unroll
    for (int j = 0; j < 8; j++) {
        const int c = 8 * j + 2 * lc;
        *(float2*)(ob0 + c) = make_float2(oacc[j][0] * inv0, oacc[j][1] * inv0);
        *(float2*)(ob1 + c) = make_float2(oacc[j][2] * inv1, oacc[j][3] * inv1);
    }
}

// ---------------------------------------------------------------------------
// Launch
// ---------------------------------------------------------------------------
extern "C" void kernel_launch(void* const* d_in, const int* in_sizes, int n_in,
                              void* d_out, int out_size) {
    const float* x    = (const float*)d_in[0];
    const float* W    = (const float*)d_in[1];
    const float* bias = (const float*)d_in[2];
    float* out = (float*)d_out;

    cvt_half<<<(unsigned)((NX4 + NW4 + 255) / 256), 256>>>(x, W);

    cudaFuncSetAttribute(qkv_gemm_tc,
                         cudaFuncAttributeMaxDynamicSharedMemorySize,
                         GEMM_SMEM_BYTES);
    qkv_gemm_tc<<<dim3(N_COLS / 128, M_ROWS / 64), 256, GEMM_SMEM_BYTES>>>(bias);

    cudaFuncSetAttribute(attn_mma,
                         cudaFuncAttributeMaxDynamicSharedMemorySize,
                         ATT_SMEM_BYTES);
    attn_mma<<<dim3(SEQ / 128, N_HEADS, BATCH), 256, ATT_SMEM_BYTES>>>(out);
}

// round 17
// speedup vs baseline: 1.0080x; 1.0080x over previous
#include <cuda_runtime.h>
#include <cuda_bf16.h>
#include <cuda_fp16.h>
#include <cstdint>
#include <math.h>

#define N_HEADS 16
#define HIDDEN  1024
#define HS      64
#define BATCH   2
#define SEQ     2048
#define M_ROWS  (BATCH * SEQ)      // 4096
#define N_COLS  (3 * HIDDEN)       // 3072

// fp16 copies of the GEMM inputs (prepass output)
__device__ __half g_xh[(size_t)M_ROWS * HIDDEN];
__device__ __half g_wh[(size_t)HIDDEN * N_COLS];
// Attention operands written by the GEMM epilogue (per (b*16+h) head):
//   Q: pre-scaled x0.125, single fp16, [t][d]
//   K: single fp16, [t][d]
//   V: single fp16, [d][t]
#define HEADELEMS ((size_t)SEQ * HS)
__device__ __half g_qh[(size_t)BATCH * N_HEADS * HEADELEMS];
__device__ __half g_kh[(size_t)BATCH * N_HEADS * HEADELEMS];
__device__ __half g_vh[(size_t)BATCH * N_HEADS * HEADELEMS];

// ---------------------------------------------------------------------------
// Helpers
// ---------------------------------------------------------------------------
__device__ __forceinline__ uint32_t smem_u32(const void* p) {
    uint32_t a;
    asm("{ .reg .u64 t; cvta.to.shared.u64 t, %1; cvt.u32.u64 %0, t; }"
        : "=r"(a) : "l"(p));
    return a;
}
__device__ __forceinline__ void mma_fp16(float* d, const uint32_t* a,
                                         const uint32_t* b) {
    asm volatile(
        "mma.sync.aligned.m16n8k16.row.col.f32.f16.f16.f32 "
        "{%0,%1,%2,%3}, {%4,%5,%6,%7}, {%8,%9}, {%0,%1,%2,%3};"
        : "+f"(d[0]), "+f"(d[1]), "+f"(d[2]), "+f"(d[3])
        : "r"(a[0]), "r"(a[1]), "r"(a[2]), "r"(a[3]),
          "r"(b[0]), "r"(b[1]));
}
__device__ __forceinline__ void ldsm_x4(uint32_t& r0, uint32_t& r1,
                                        uint32_t& r2, uint32_t& r3,
                                        uint32_t addr) {
    asm volatile("ldmatrix.sync.aligned.m8n8.x4.shared.b16 {%0,%1,%2,%3}, [%4];"
                 : "=r"(r0), "=r"(r1), "=r"(r2), "=r"(r3) : "r"(addr));
}
__device__ __forceinline__ void ldsm_x4_t(uint32_t& r0, uint32_t& r1,
                                          uint32_t& r2, uint32_t& r3,
                                          uint32_t addr) {
    asm volatile("ldmatrix.sync.aligned.m8n8.x4.trans.shared.b16 {%0,%1,%2,%3}, [%4];"
                 : "=r"(r0), "=r"(r1), "=r"(r2), "=r"(r3) : "r"(addr));
}
__device__ __forceinline__ uint32_t pack_h2(float x, float y) {
    __half2 h = __floats2half2_rn(x, y);
    return *reinterpret_cast<uint32_t*>(&h);
}
__device__ __forceinline__ void cp16(uint32_t dst, const void* src) {
    asm volatile("cp.async.cg.shared.global [%0], [%1], 16;"
                 :: "r"(dst), "l"(src) : "memory");
}
#define CP_COMMIT() asm volatile("cp.async.commit_group;" ::: "memory")
#define CP_WAIT1()  asm volatile("cp.async.wait_group 1;" ::: "memory")
#define CP_WAIT0()  asm volatile("cp.async.wait_group 0;" ::: "memory")

// ---------------------------------------------------------------------------
// Kernel 0: fp32 -> fp16 prepass for x and W.
// ---------------------------------------------------------------------------
#define NX4 ((size_t)M_ROWS * HIDDEN / 4)   // 1048576
#define NW4 ((size_t)HIDDEN * N_COLS / 4)   // 786432

__global__ void __launch_bounds__(256) cvt_half(const float* __restrict__ x,
                                                const float* __restrict__ W) {
    size_t i = (size_t)blockIdx.x * 256 + threadIdx.x;
    if (i < NX4) {
        float4 v = ((const float4*)x)[i];
        __half2* dst = (__half2*)(g_xh + i * 4);
        dst[0] = __floats2half2_rn(v.x, v.y);
        dst[1] = __floats2half2_rn(v.z, v.w);
    } else if (i < NX4 + NW4) {
        size_t j = i - NX4;
        float4 v = ((const float4*)W)[j];
        __half2* dst = (__half2*)(g_wh + j * 4);
        dst[0] = __floats2half2_rn(v.x, v.y);
        dst[1] = __floats2half2_rn(v.z, v.w);
    }
}

// ---------------------------------------------------------------------------
// Kernel 1: QKV GEMM via mma.sync fp16 m16n8k16, ldmatrix fragments.
// 64x128 CTA tile, GBK=64 (16 iters), 3 CTAs/SM, 1536 CTAs:
//   - quantization: max 11 CTAs/SM vs 10.38 avg = 6% (was 6/5.19 = 16%)
//   - per-iter overhead amortized over 32 mma/warp (R15 level)
// Stages built from PROVEN sub-tile layouts:
//   A stage = 2x [64 m][32 k] halfs @ 80B rows (5120B each, offset sub*5120)
//   B stage = 2x [32 k][128 n] halfs @ 256B rows, col^((k&7)<<4)
//             (8192B each, offset 10240 + sub*8192)
// Compute: ks in 0..3 -> sub = ks>>1, kk = ks&1 with the R15 formulas.
// Epilogue: bias + reshape scatter (g = 3r + c/1024; e = c%1024; u=g>>11;
// t=g&2047; h=e&15; d=e>>4): Q x0.125 fp16 [t][d], K fp16 [t][d],
// V fp16 [d][t].
// ---------------------------------------------------------------------------
#define GBK   64
#define GNIT  (HIDDEN / GBK)          // 16
#define CSTR  132
#define AST_B 10240                   // A stage bytes (2 x 64*80)
#define BST_B 16384                   // B stage bytes (2 x 8192)
#define STG_B (AST_B + BST_B)         // 26624
#define GEMM_SMEM_BYTES (2 * STG_B)   // 53248 >= epilogue 33792

__global__ void __launch_bounds__(256, 3) qkv_gemm_tc(const float* __restrict__ bias)
{
    extern __shared__ char smc[];
    const uint32_t sbase = smem_u32(smc);
    const int tid  = threadIdx.x;
    const int lane = tid & 31;
    const int wid  = tid >> 5;
    const int wm   = wid & 1;          // 2 warps along M (32 rows each)
    const int wn   = wid >> 1;         // 4 warps along N (32 cols each)
    const int m0 = blockIdx.y * 64, n0 = blockIdx.x * 128;
    const int lr = lane >> 2, lc = lane & 3;

    // cp.async mapping per iter: A 2 chunks + B 4 chunks (16B each) / thread
    uint32_t a_dst[2];
    const __half* a_src[2];
    #pragma unroll
    for (int i = 0; i < 2; i++) {
        int id = tid + i * 256;            // 0..511
        int am = id >> 3, ac = id & 7;     // 64 rows x 8 k-chunks
        a_dst[i] = (uint32_t)((ac >> 2) * 5120 + am * 80 + (ac & 3) * 16);
        a_src[i] = g_xh + (size_t)(m0 + am) * HIDDEN + ac * 8;
    }
    uint32_t b_dst[4];
    const __half* b_src[4];
    #pragma unroll
    for (int i = 0; i < 4; i++) {
        int id = tid + i * 256;            // 0..1023
        int bk = id >> 4, bc = id & 15;    // 64 k-rows x 16 n-chunks
        b_dst[i] = (uint32_t)(AST_B + (bk >> 5) * 8192 + (bk & 31) * 256
                              + ((bc * 16) ^ ((bk & 7) << 4)));
        b_src[i] = g_wh + (size_t)bk * N_COLS + n0 + bc * 8;
    }

    // ldmatrix lane decomposition (g = matrix index, r = row within matrix)
    const int g = lane >> 3, r = lane & 7;
    const uint32_t a_lane = (uint32_t)((wm * 32 + ((g & 1) << 3) + r) * 80
                                       + (((g >> 1) << 3) << 1));
    const uint32_t b_rowb  = (uint32_t)((((g & 1) << 3) + r) * 256);
    const uint32_t b_colh0 = (uint32_t)(wn * 32 + ((g >> 1) << 3));
    const uint32_t b_xor   = (uint32_t)(r << 4);

    float acc[2][4][4] = {};

    // Prologue: stage 0
    #pragma unroll
    for (int i = 0; i < 2; i++) cp16(sbase + a_dst[i], a_src[i]);
    #pragma unroll
    for (int i = 0; i < 4; i++) cp16(sbase + b_dst[i], b_src[i]);
    CP_COMMIT();

    for (int it = 0; it < GNIT; ++it) {
        const uint32_t buf = (uint32_t)(it & 1) * STG_B;
        if (it + 1 < GNIT) {
            const uint32_t nb = (uint32_t)((it + 1) & 1) * STG_B;
            #pragma unroll
            for (int i = 0; i < 2; i++)
                cp16(sbase + nb + a_dst[i], a_src[i] + (it + 1) * GBK);
            #pragma unroll
            for (int i = 0; i < 4; i++)
                cp16(sbase + nb + b_dst[i], b_src[i] + (size_t)(it + 1) * GBK * N_COLS);
            CP_COMMIT();
            CP_WAIT1();
        } else {
            CP_WAIT0();
        }
        __syncthreads();

        #pragma unroll
        for (int ks = 0; ks < 4; ks++) {
            const uint32_t asub = (uint32_t)(ks >> 1) * 5120;
            const uint32_t bsub = (uint32_t)(ks >> 1) * 8192;
            const uint32_t kk   = (uint32_t)(ks & 1);
            uint32_t bf[4][2];
            #pragma unroll
            for (int nblk = 0; nblk < 2; nblk++) {
                uint32_t baddr = sbase + buf + AST_B + bsub + b_rowb + kk * 4096
                               + ((((b_colh0 + nblk * 16) << 1)) ^ b_xor);
                uint32_t r0, r1, r2, r3;
                ldsm_x4_t(r0, r1, r2, r3, baddr);
                bf[nblk * 2 + 0][0] = r0; bf[nblk * 2 + 0][1] = r1;
                bf[nblk * 2 + 1][0] = r2; bf[nblk * 2 + 1][1] = r3;
            }
            #pragma unroll
            for (int mf = 0; mf < 2; mf++) {
                uint32_t af[4];
                ldsm_x4(af[0], af[1], af[2], af[3],
                        sbase + buf + asub + a_lane + mf * 1280 + kk * 32);
                #pragma unroll
                for (int nf = 0; nf < 4; nf++)
                    mma_fp16(acc[mf][nf], af, bf[nf]);
            }
        }
        __syncthreads();
    }

    // ---- Epilogue via smem (64 rows x 128 cols) ----
    float* Cs = (float*)smc;
    #pragma unroll
    for (int mf = 0; mf < 2; mf++) {
        const int rr = wm * 32 + mf * 16 + lr;
        #pragma unroll
        for (int nf = 0; nf < 4; nf++) {
            const int c = wn * 32 + nf * 8 + 2 * lc;
            *(float2*)&Cs[rr * CSTR + c]       = make_float2(acc[mf][nf][0], acc[mf][nf][1]);
            *(float2*)&Cs[(rr + 8) * CSTR + c] = make_float2(acc[mf][nf][2], acc[mf][nf][3]);
        }
    }
    __syncthreads();

    {
        const int rr = tid >> 2;            // 0..63 local row
        const int quarter = tid & 3;        // 4 heads per thread
        const int rglob = m0 + rr;
        const int gg = 3 * rglob + (n0 >> 10);
        const int u = gg >> 11, t = gg & 2047;
        const int d0 = (n0 & 1023) >> 4;
        const int kind = u >> 1;            // 0=Q, 1=K, 2=V
        const int bb = u & 1;               // batch
        #pragma unroll
        for (int j = 0; j < 4; j++) {
            const int hh = quarter * 4 + j;
            float o[8];
            #pragma unroll
            for (int e = 0; e < 8; e++)
                o[e] = Cs[rr * CSTR + hh + 16 * e] + __ldg(&bias[n0 + hh + 16 * e]);
            const size_t head = (size_t)(bb * 16 + hh) * HEADELEMS;
            if (kind == 2) {
                // V: single fp16, [d][t]
                #pragma unroll
                for (int e = 0; e < 8; e++)
                    g_vh[head + (size_t)(d0 + e) * SEQ + t] = __float2half_rn(o[e]);
            } else {
                // Q (scaled) or K: single fp16, [t][d]
                const float sc = (kind == 0) ? 0.125f : 1.0f;
                uint32_t kk[4];
                #pragma unroll
                for (int p = 0; p < 4; p++)
                    kk[p] = pack_h2(o[2 * p] * sc, o[2 * p + 1] * sc);
                __half* dst = (kind == 0) ? g_qh : g_kh;
                *(uint4*)(dst + head + (size_t)t * HS + d0) =
                    make_uint4(kk[0], kk[1], kk[2], kk[3]);
            }
        }
    }
}

// ---------------------------------------------------------------------------
// Kernel 2: flash attention via mma.sync fp16 m16n8k16 (byte-identical R15).
// Q, K, V, P all single fp16: QK = 1 mma, PV = 1 mma -> 64 mma/warp-tile.
// SMEM (u32): Q 0..4095; KV double buffers at 4096 + buf*4096:
//   K +0 (2048), V +2048 (2048). Total 12288 u32 = 48KB.
// ---------------------------------------------------------------------------
#define ATT_SMEM_BYTES (12288 * 4)

__global__ void __launch_bounds__(256, 2) attn_mma(float* __restrict__ out) {
    extern __shared__ uint32_t sm[];
    const uint32_t sb = smem_u32(sm);
    uint32_t* Qs = sm;

    const int tid  = threadIdx.x;
    const int lane = tid & 31;
    const int w    = tid >> 5;          // warp 0..7, rows [16w,16w+16)
    const int lr   = lane >> 2, lc = lane & 3;
    const int qtile = (int)(gridDim.x - 1) - (int)blockIdx.x;  // long CTAs first
    const int h = blockIdx.y, b = blockIdx.z;
    const int q0 = qtile * 128;

    const size_t head = (size_t)(b * 16 + h) * HEADELEMS;
    const __half* qhg = g_qh + head;
    const __half* khg = g_kh + head;
    const __half* vhg = g_vh + head;

    uint32_t kv_dst[2];
    int      kv_row[2], kv_c[2];
    #pragma unroll
    for (int i = 0; i < 2; i++) {
        int id = tid + i * 256;
        kv_row[i] = id >> 3;
        kv_c[i]   = id & 7;
        kv_dst[i] = (uint32_t)((kv_row[i] * 32 + ((kv_c[i] ^ (kv_row[i] & 7)) << 2)) * 4);
    }

    // ---- Prologue: Q + KV tile 0 (one group) ----
    #pragma unroll
    for (int i = 0; i < 4; i++) {
        int id = tid + i * 256;
        int rq = id >> 3, cq = id & 7;
        uint32_t d = (uint32_t)((rq * 32 + ((cq ^ (rq & 7)) << 2)) * 4);
        cp16(sb + d, qhg + (size_t)(q0 + rq) * HS + cq * 8);
    }
    #pragma unroll
    for (int i = 0; i < 2; i++) {
        uint32_t base = sb + 4096 * 4;
        cp16(base + kv_dst[i],        khg + (size_t)kv_row[i] * HS + kv_c[i] * 8);
        cp16(base + 8192 + kv_dst[i], vhg + (size_t)kv_row[i] * SEQ + kv_c[i] * 8);
    }
    CP_COMMIT();

    float oacc[8][4];
    #pragma unroll
    for (int j = 0; j < 8; j++)
        #pragma unroll
        for (int k = 0; k < 4; k++) oacc[j][k] = 0.0f;
    float m0 = -1e30f, m1 = -1e30f, l0 = 0.0f, l1 = 0.0f;

    const uint32_t xmask = (uint32_t)lr << 2;

    const int nkt = 2 * qtile + 2;
    for (int kt = 0; kt < nkt; kt++) {
        const int k0g = kt * 64;
        if (kt + 1 < nkt) {
            const int k0n = (kt + 1) * 64;
            const uint32_t base = sb + (4096 + ((kt + 1) & 1) * 4096) * 4;
            #pragma unroll
            for (int i = 0; i < 2; i++) {
                cp16(base + kv_dst[i],        khg + (size_t)(k0n + kv_row[i]) * HS + kv_c[i] * 8);
                cp16(base + 8192 + kv_dst[i], vhg + (size_t)kv_row[i] * SEQ + k0n + kv_c[i] * 8);
            }
            CP_COMMIT();
            CP_WAIT1();
        } else {
            CP_WAIT0();
        }
        __syncthreads();

        if (k0g <= q0 + 16 * w + 15) {
            const uint32_t* Kb = sm + 4096 + (kt & 1) * 4096;
            const uint32_t* Vb = Kb + 2048;

            float sacc[8][4];
            #pragma unroll
            for (int j = 0; j < 8; j++)
                #pragma unroll
                for (int k = 0; k < 4; k++) sacc[j][k] = 0.0f;

            const int r = 16 * w + lr;
            const uint32_t qbase = r * 32;
            #pragma unroll
            for (int ks = 0; ks < 4; ks++) {
                const uint32_t c1x = ((uint32_t)(8 * ks + lc)) ^ xmask;
                const uint32_t c2x = ((uint32_t)(8 * ks + lc + 4)) ^ xmask;
                uint32_t aq[4];
                aq[0] = Qs[qbase + c1x];
                aq[1] = Qs[qbase + 256 + c1x];
                aq[2] = Qs[qbase + c2x];
                aq[3] = Qs[qbase + 256 + c2x];
                #pragma unroll
                for (int j = 0; j < 8; j++) {
                    const uint32_t nb = (uint32_t)(8 * j + lr) * 32;
                    uint32_t bh[2] = { Kb[nb + c1x], Kb[nb + c2x] };
                    mma_fp16(sacc[j], aq, bh);
                }
            }

            const int row0 = q0 + 16 * w + lr;
            if (k0g + 63 > q0 + 16 * w) {
                #pragma unroll
                for (int j = 0; j < 8; j++) {
                    const int c0 = k0g + 8 * j + 2 * lc;
                    if (c0 > row0)         sacc[j][0] = -1e30f;
                    if (c0 + 1 > row0)     sacc[j][1] = -1e30f;
                    if (c0 > row0 + 8)     sacc[j][2] = -1e30f;
                    if (c0 + 1 > row0 + 8) sacc[j][3] = -1e30f;
                }
            }

            float ml0 = -1e30f, ml1 = -1e30f;
            #pragma unroll
            for (int j = 0; j < 8; j++) {
                ml0 = fmaxf(ml0, fmaxf(sacc[j][0], sacc[j][1]));
                ml1 = fmaxf(ml1, fmaxf(sacc[j][2], sacc[j][3]));
            }
            ml0 = fmaxf(ml0, __shfl_xor_sync(0xffffffffu, ml0, 1));
            ml0 = fmaxf(ml0, __shfl_xor_sync(0xffffffffu, ml0, 2));
            ml1 = fmaxf(ml1, __shfl_xor_sync(0xffffffffu, ml1, 1));
            ml1 = fmaxf(ml1, __shfl_xor_sync(0xffffffffu, ml1, 2));

            const float mn0 = fmaxf(m0, ml0), mn1 = fmaxf(m1, ml1);
            const float fac0 = __expf(m0 - mn0), fac1 = __expf(m1 - mn1);
            float ls0 = 0.0f, ls1 = 0.0f;
            #pragma unroll
            for (int j = 0; j < 8; j++) {
                float p0 = __expf(sacc[j][0] - mn0);
                float p1 = __expf(sacc[j][1] - mn0);
                float p2 = __expf(sacc[j][2] - mn1);
                float p3 = __expf(sacc[j][3] - mn1);
                sacc[j][0] = p0; sacc[j][1] = p1; sacc[j][2] = p2; sacc[j][3] = p3;
                ls0 += p0 + p1; ls1 += p2 + p3;
            }
            ls0 += __shfl_xor_sync(0xffffffffu, ls0, 1);
            ls0 += __shfl_xor_sync(0xffffffffu, ls0, 2);
            ls1 += __shfl_xor_sync(0xffffffffu, ls1, 1);
            ls1 += __shfl_xor_sync(0xffffffffu, ls1, 2);
            l0 = l0 * fac0 + ls0;
            l1 = l1 * fac1 + ls1;
            m0 = mn0; m1 = mn1;

            #pragma unroll
            for (int j = 0; j < 8; j++) {
                oacc[j][0] *= fac0; oacc[j][1] *= fac0;
                oacc[j][2] *= fac1; oacc[j][3] *= fac1;
            }

            #pragma unroll
            for (int ks = 0; ks < 4; ks++) {
                uint32_t pf[4];
                pf[0] = pack_h2(sacc[2 * ks][0],     sacc[2 * ks][1]);
                pf[1] = pack_h2(sacc[2 * ks][2],     sacc[2 * ks][3]);
                pf[2] = pack_h2(sacc[2 * ks + 1][0], sacc[2 * ks + 1][1]);
                pf[3] = pack_h2(sacc[2 * ks + 1][2], sacc[2 * ks + 1][3]);
                const uint32_t c1x = ((uint32_t)(8 * ks + lc)) ^ xmask;
                const uint32_t c2x = ((uint32_t)(8 * ks + lc + 4)) ^ xmask;
                #pragma unroll
                for (int j = 0; j < 8; j++) {
                    const uint32_t nb = (uint32_t)(8 * j + lr) * 32;
                    uint32_t bv[2] = { Vb[nb + c1x], Vb[nb + c2x] };
                    mma_fp16(oacc[j], pf, bv);
                }
            }
        }
        __syncthreads();
    }

    // ---- Write O, normalized ----
    const float inv0 = 1.0f / l0, inv1 = 1.0f / l1;
    const int row = q0 + 16 * w + lr;
    float* ob0 = out + ((size_t)(b * SEQ + row)) * HIDDEN + h * HS;
    float* ob1 = out + ((size_t)(b * SEQ + row + 8)) * HIDDEN + h * HS;
    #pragma unroll
    for (int j = 0; j < 8; j++) {
        const int c = 8 * j + 2 * lc;
        *(float2*)(ob0 + c) = make_float2(oacc[j][0] * inv0, oacc[j][1] * inv0);
        *(float2*)(ob1 + c) = make_float2(oacc[j][2] * inv1, oacc[j][3] * inv1);
    }
}

// ---------------------------------------------------------------------------
// Launch
// ---------------------------------------------------------------------------
extern "C" void kernel_launch(void* const* d_in, const int* in_sizes, int n_in,
                              void* d_out, int out_size) {
    const float* x    = (const float*)d_in[0];
    const float* W    = (const float*)d_in[1];
    const float* bias = (const float*)d_in[2];
    float* out = (float*)d_out;

    cvt_half<<<(unsigned)((NX4 + NW4 + 255) / 256), 256>>>(x, W);

    cudaFuncSetAttribute(qkv_gemm_tc,
                         cudaFuncAttributeMaxDynamicSharedMemorySize,
                         GEMM_SMEM_BYTES);
    qkv_gemm_tc<<<dim3(N_COLS / 128, M_ROWS / 64), 256, GEMM_SMEM_BYTES>>>(bias);

    cudaFuncSetAttribute(attn_mma,
                         cudaFuncAttributeMaxDynamicSharedMemorySize,
                         ATT_SMEM_BYTES);
    attn_mma<<<dim3(SEQ / 128, N_HEADS, BATCH), 256, ATT_SMEM_BYTES>>>(out);
}